// round 2
// baseline (speedup 1.0000x reference)
#include <cuda_runtime.h>

// ---------------- problem constants ----------------
#define HID   128
#define BGR   64       // graphs
#define NPG   64       // nodes per graph
#define NN    4096     // total nodes (BGR*NPG)
#define PPG   2016     // pairs per graph
#define PTOT  129024   // total pairs (BGR*PPG)
#define OUTD  10

// ---------------- device scratch (no allocation allowed) ----------------
__device__ float g_hN  [NN * HID];
__device__ float g_preN[NN * HID];
__device__ float g_msgN[NN * HID];
__device__ float g_HA  [NN * HID];
__device__ float g_HB  [NN * HID];
__device__ float g_MA  [NN * HID];
__device__ float g_MB  [NN * HID];
__device__ float g_pre2[(size_t)PTOT * HID];   // 66 MB
__device__ float g_h2  [(size_t)PTOT * HID];   // 66 MB
__device__ float g_M2  [(size_t)PTOT * HID];   // 66 MB
__device__ float g_comb[BGR * 2 * HID];
__device__ int   g_idx_stride;                 // 1 if indices int32, 2 if int64

// ---------------- index dtype detection ----------------
// batch = repeat(arange(64), 64). Viewed as int32 words:
//   int32 layout -> word[64] == 1 ; int64 layout -> word[64] == 0.
__global__ void detect_stride_k(const int* __restrict__ batch_words) {
    if (threadIdx.x == 0) g_idx_stride = (batch_words[64] == 1) ? 1 : 2;
}

// ---------------- dual GEMM: C1 = A@W1, C2 = A@W2 ; N = 128 ----------------
__global__ __launch_bounds__(256) void gemm2_k(
    const float* __restrict__ A, const float* __restrict__ W1,
    const float* __restrict__ W2, float* __restrict__ C1,
    float* __restrict__ C2, int M, int K)
{
    __shared__ float sA [16][64];
    __shared__ float sW1[16][128];
    __shared__ float sW2[16][128];

    const int tid = threadIdx.x;
    const int tx = tid & 15, ty = tid >> 4;
    const int m0 = blockIdx.x * 64;
    const int r0 = ty * 4, c0 = tx * 8;

    float acc1[4][8];
    float acc2[4][8];
    #pragma unroll
    for (int i = 0; i < 4; i++)
        #pragma unroll
        for (int j = 0; j < 8; j++) { acc1[i][j] = 0.f; acc2[i][j] = 0.f; }

    for (int kt = 0; kt < K; kt += 16) {
        {
            int idx = tid * 4;
            int m = idx >> 4, kk = idx & 15;
            float4 a = *(const float4*)&A[(size_t)(m0 + m) * K + kt + kk];
            sA[kk + 0][m] = a.x; sA[kk + 1][m] = a.y;
            sA[kk + 2][m] = a.z; sA[kk + 3][m] = a.w;
        }
        #pragma unroll
        for (int j = 0; j < 2; j++) {
            int idx4 = tid * 2 + j;           // 0..511
            int kk = idx4 >> 5, c4 = idx4 & 31;
            *(float4*)&sW1[kk][c4 * 4] = *(const float4*)&W1[(size_t)(kt + kk) * 128 + c4 * 4];
            *(float4*)&sW2[kk][c4 * 4] = *(const float4*)&W2[(size_t)(kt + kk) * 128 + c4 * 4];
        }
        __syncthreads();

        #pragma unroll
        for (int kk = 0; kk < 16; kk++) {
            float a[4];
            #pragma unroll
            for (int i = 0; i < 4; i++) a[i] = sA[kk][r0 + i];
            float4 w1a = *(float4*)&sW1[kk][c0];
            float4 w1b = *(float4*)&sW1[kk][c0 + 4];
            float4 w2a = *(float4*)&sW2[kk][c0];
            float4 w2b = *(float4*)&sW2[kk][c0 + 4];
            float w1[8] = {w1a.x, w1a.y, w1a.z, w1a.w, w1b.x, w1b.y, w1b.z, w1b.w};
            float w2[8] = {w2a.x, w2a.y, w2a.z, w2a.w, w2b.x, w2b.y, w2b.z, w2b.w};
            #pragma unroll
            for (int i = 0; i < 4; i++)
                #pragma unroll
                for (int j = 0; j < 8; j++) {
                    acc1[i][j] += a[i] * w1[j];
                    acc2[i][j] += a[i] * w2[j];
                }
        }
        __syncthreads();
    }

    #pragma unroll
    for (int i = 0; i < 4; i++) {
        size_t row = (size_t)(m0 + r0 + i) * 128 + c0;
        *(float4*)&C1[row]     = make_float4(acc1[i][0], acc1[i][1], acc1[i][2], acc1[i][3]);
        *(float4*)&C1[row + 4] = make_float4(acc1[i][4], acc1[i][5], acc1[i][6], acc1[i][7]);
        *(float4*)&C2[row]     = make_float4(acc2[i][0], acc2[i][1], acc2[i][2], acc2[i][3]);
        *(float4*)&C2[row + 4] = make_float4(acc2[i][4], acc2[i][5], acc2[i][6], acc2[i][7]);
    }
}

// ---------------- edge scatter: pre[dst] += msg[src] ----------------
// edge_index is [2, E] row-major; src row at word offset 0, dst row at word
// offset E*stride. Both handled via on-device stride: dst index = (e + E).
__global__ void scatter_k(const int* __restrict__ eidx,
                          const float* __restrict__ msg, float* __restrict__ pre, int E)
{
    int idx = blockIdx.x * blockDim.x + threadIdx.x;
    int total = E * 32;
    if (idx >= total) return;
    int e = idx >> 5, c4 = idx & 31;
    int st = g_idx_stride;
    int s = eidx[(size_t)e * st];
    int d = eidx[(size_t)(e + E) * st];
    float4 m = ((const float4*)msg)[(size_t)s * 32 + c4];
    float* p = &pre[(size_t)d * 128 + c4 * 4];
    atomicAdd(p + 0, m.x); atomicAdd(p + 1, m.y);
    atomicAdd(p + 2, m.z); atomicAdd(p + 3, m.w);
}

// ---------------- relu (vectorized) ----------------
__global__ void krelu(const float* __restrict__ in, float* __restrict__ out, int n4)
{
    int i = blockIdx.x * blockDim.x + threadIdx.x;
    if (i >= n4) return;
    float4 v = ((const float4*)in)[i];
    v.x = fmaxf(v.x, 0.f); v.y = fmaxf(v.y, 0.f);
    v.z = fmaxf(v.z, 0.f); v.w = fmaxf(v.w, 0.f);
    ((float4*)out)[i] = v;
}

// ---------------- pair build ----------------
__global__ void pair_build_k(const int* __restrict__ pu, const int* __restrict__ pv,
                             const float* __restrict__ iso,
                             const float* __restrict__ HA, const float* __restrict__ HB,
                             const float* __restrict__ MA, const float* __restrict__ MB,
                             const float* __restrict__ w1r, const float* __restrict__ w2r,
                             float* __restrict__ pre2, float* __restrict__ msg2)
{
    int idx = blockIdx.x * blockDim.x + threadIdx.x;
    const int total = PTOT * 32;
    if (idx >= total) return;
    int p = idx >> 5, c4 = idx & 31;
    int st = g_idx_stride;
    int u = pu[(size_t)p * st];
    int v = pv[(size_t)p * st];
    float is = iso[p];

    float4 a = ((const float4*)HA)[(size_t)u * 32 + c4];
    float4 b = ((const float4*)HB)[(size_t)v * 32 + c4];
    float4 w = ((const float4*)w1r)[c4];
    float4 o;
    o.x = a.x + b.x + is * w.x; o.y = a.y + b.y + is * w.y;
    o.z = a.z + b.z + is * w.z; o.w = a.w + b.w + is * w.w;
    ((float4*)pre2)[(size_t)p * 32 + c4] = o;

    float4 ma = ((const float4*)MA)[(size_t)u * 32 + c4];
    float4 mb = ((const float4*)MB)[(size_t)v * 32 + c4];
    float4 w2 = ((const float4*)w2r)[c4];
    float4 m;
    m.x = ma.x + mb.x + is * w2.x; m.y = ma.y + mb.y + is * w2.y;
    m.z = ma.z + mb.z + is * w2.z; m.w = ma.w + mb.w + is * w2.w;
    ((float4*)msg2)[(size_t)p * 32 + c4] = m;
}

// ---------------- graph embeddings ----------------
__global__ void zero_comb_k(float* __restrict__ comb)
{
    int i = blockIdx.x * blockDim.x + threadIdx.x;
    if (i < BGR * 2 * HID) comb[i] = 0.f;
}

__global__ void ge1_k(const float* __restrict__ h, float* __restrict__ comb)
{
    int g = blockIdx.x, c = threadIdx.x;
    float s = 0.f;
    for (int i = 0; i < NPG; i++) s += h[(size_t)(g * NPG + i) * HID + c];
    comb[g * 256 + c] = s;
}

__global__ void ge2_k(const float* __restrict__ pre2, float* __restrict__ comb)
{
    int g = blockIdx.x, chunk = blockIdx.y, c = threadIdx.x;
    int rbeg = chunk * 252, rend = rbeg + 252;   // 2016 = 8 * 252
    float s = 0.f;
    for (int i = rbeg; i < rend; i++) {
        float v = pre2[(size_t)(g * PPG + i) * HID + c];
        s += fmaxf(v, 0.f);
    }
    atomicAdd(&comb[g * 256 + 128 + c], s);
}

// ---------------- final classifier ----------------
__global__ void final_k(const float* __restrict__ comb,
                        const float* __restrict__ W0, const float* __restrict__ b0,
                        const float* __restrict__ W1, const float* __restrict__ b1,
                        float* __restrict__ out)
{
    __shared__ float sc[256];
    __shared__ float shc[128];
    int g = blockIdx.x, tid = threadIdx.x;
    sc[tid] = comb[g * 256 + tid];
    sc[tid + 128] = comb[g * 256 + 128 + tid];
    __syncthreads();

    float acc = b0[tid];
    #pragma unroll 8
    for (int k = 0; k < 256; k++) acc += sc[k] * W0[(size_t)k * 128 + tid];
    shc[tid] = fmaxf(acc, 0.f);
    __syncthreads();

    if (tid < OUTD) {
        float o = b1[tid];
        #pragma unroll 8
        for (int k = 0; k < 128; k++) o += shc[k] * W1[(size_t)k * OUTD + tid];
        out[g * OUTD + tid] = o;
    }
}

// ---------------- launch ----------------
extern "C" void kernel_launch(void* const* d_in, const int* in_sizes, int n_in,
                              void* d_out, int out_size)
{
    const float* x      = (const float*)d_in[0];
    const float* W1_0   = (const float*)d_in[1];
    const float* W2_0   = (const float*)d_in[2];
    const float* W1_1   = (const float*)d_in[3];
    const float* W2_1   = (const float*)d_in[4];
    const float* W1_2   = (const float*)d_in[5];
    const float* W2_2   = (const float*)d_in[6];
    const float* kW10   = (const float*)d_in[7];   // [257,128]
    const float* kW20   = (const float*)d_in[8];   // [257,128]
    const float* kW11   = (const float*)d_in[9];   // [128,128]
    const float* kW21   = (const float*)d_in[10];  // [128,128]
    const float* cW0    = (const float*)d_in[11];  // [256,128]
    const float* cb0    = (const float*)d_in[12];
    const float* cW1    = (const float*)d_in[13];  // [128,10]
    const float* cb1    = (const float*)d_in[14];
    const float* iso    = (const float*)d_in[15];  // [129024]
    const int*   ei     = (const int*)d_in[16];    // [2,E1] words
    const int*   batch  = (const int*)d_in[17];
    const int*   pu     = (const int*)d_in[18];
    const int*   pv     = (const int*)d_in[19];
    const int*   te     = (const int*)d_in[20];    // [2,E2] words
    float*       out    = (float*)d_out;

    const int E1 = in_sizes[16] / 2;
    const int E2 = in_sizes[20] / 2;

    float *hN, *preN, *msgN, *HA, *HB, *MA, *MB, *pre2, *h2, *M2, *comb;
    cudaGetSymbolAddress((void**)&hN,   g_hN);
    cudaGetSymbolAddress((void**)&preN, g_preN);
    cudaGetSymbolAddress((void**)&msgN, g_msgN);
    cudaGetSymbolAddress((void**)&HA,   g_HA);
    cudaGetSymbolAddress((void**)&HB,   g_HB);
    cudaGetSymbolAddress((void**)&MA,   g_MA);
    cudaGetSymbolAddress((void**)&MB,   g_MB);
    cudaGetSymbolAddress((void**)&pre2, g_pre2);
    cudaGetSymbolAddress((void**)&h2,   g_h2);
    cudaGetSymbolAddress((void**)&M2,   g_M2);
    cudaGetSymbolAddress((void**)&comb, g_comb);

    detect_stride_k<<<1, 32>>>(batch);

    const int sblocks  = (E1 * 32 + 255) / 256;
    const int rblocksN = (NN * 32 + 255) / 256;

    // node GNN, 3 layers
    gemm2_k<<<NN / 64, 256>>>(x, W1_0, W2_0, preN, msgN, NN, 64);
    scatter_k<<<sblocks, 256>>>(ei, msgN, preN, E1);
    krelu<<<rblocksN, 256>>>(preN, hN, NN * 32);

    gemm2_k<<<NN / 64, 256>>>(hN, W1_1, W2_1, preN, msgN, NN, 128);
    scatter_k<<<sblocks, 256>>>(ei, msgN, preN, E1);
    krelu<<<rblocksN, 256>>>(preN, hN, NN * 32);

    gemm2_k<<<NN / 64, 256>>>(hN, W1_2, W2_2, preN, msgN, NN, 128);
    scatter_k<<<sblocks, 256>>>(ei, msgN, preN, E1);
    krelu<<<rblocksN, 256>>>(preN, hN, NN * 32);

    // 2-set input layer, decomposed
    gemm2_k<<<NN / 64, 256>>>(hN, kW10, kW10 + 128 * 128, HA, HB, NN, 128);
    gemm2_k<<<NN / 64, 256>>>(hN, kW20, kW20 + 128 * 128, MA, MB, NN, 128);

    pair_build_k<<<(PTOT * 32 + 255) / 256, 256>>>(
        pu, pv, iso, HA, HB, MA, MB,
        kW10 + 256 * 128, kW20 + 256 * 128, pre2, M2);

    const int s2blocks = (E2 * 32 + 255) / 256;
    const int rblocksP = (PTOT * 32 + 255) / 256;
    scatter_k<<<s2blocks, 256>>>(te, M2, pre2, E2);
    krelu<<<rblocksP, 256>>>(pre2, h2, PTOT * 32);

    // 2-set layer 1 (dominant GEMM pair)
    gemm2_k<<<PTOT / 64, 256>>>(h2, kW11, kW21, pre2, M2, PTOT, 128);
    scatter_k<<<s2blocks, 256>>>(te, M2, pre2, E2);

    // readout
    zero_comb_k<<<(BGR * 256 + 255) / 256, 256>>>(comb);
    ge1_k<<<BGR, 128>>>(hN, comb);
    dim3 g2grid(BGR, 8);
    ge2_k<<<g2grid, 128>>>(pre2, comb);
    final_k<<<BGR, 128>>>(comb, cW0, cb0, cW1, cb1, out);
}

// round 3
// speedup vs baseline: 1.2306x; 1.2306x over previous
#include <cuda_runtime.h>

// ---------------- problem constants ----------------
#define HID   128
#define BGR   64       // graphs
#define NPG   64       // nodes per graph
#define NN    4096     // total nodes (BGR*NPG)
#define PPG   2016     // pairs per graph
#define PTOT  129024   // total pairs (BGR*PPG)
#define OUTD  10

// ---------------- device scratch (no allocation allowed) ----------------
__device__ float g_bufA[NN * HID];
__device__ float g_bufB[NN * HID];
__device__ float g_msgN[NN * HID];
__device__ float g_HA  [NN * HID];
__device__ float g_HB  [NN * HID];
__device__ float g_MA  [NN * HID];
__device__ float g_MB  [NN * HID];
__device__ float g_pre2[(size_t)PTOT * HID];   // 66 MB
__device__ float g_h2  [(size_t)PTOT * HID];   // 66 MB
__device__ float g_M2  [(size_t)PTOT * HID];   // 66 MB
__device__ float g_comb[BGR * 2 * HID];
__device__ int   g_idx_stride;                 // 1 if indices int32, 2 if int64

// ---------------- index dtype detection ----------------
// batch = repeat(arange(64), 64). Viewed as int32 words:
//   int32 layout -> word[64] == 1 ; int64 layout -> word[64] == 0.
__global__ void detect_stride_k(const int* __restrict__ batch_words) {
    if (threadIdx.x == 0) g_idx_stride = (batch_words[64] == 1) ? 1 : 2;
}

// ---------------- packed f32x2 helpers ----------------
__device__ __forceinline__ void ffma2(unsigned long long& acc,
                                      unsigned long long a,
                                      unsigned long long b) {
    asm("fma.rn.f32x2 %0, %1, %2, %0;" : "+l"(acc) : "l"(a), "l"(b));
}
__device__ __forceinline__ unsigned long long bcast2(float x) {
    unsigned long long d;
    asm("mov.b64 %0, {%1, %1};" : "=l"(d) : "f"(x));
    return d;
}

// ---------------- dual GEMM (FFMA2): C1 = A'@W1, C2 = A'@W2 ; N = 128 ----------------
// A' = relu(A) if RELU_A. Block = 64 rows x 128 cols, 256 threads.
template <int RELU_A>
__global__ __launch_bounds__(256) void gemm2f2_k(
    const float* __restrict__ A, const float* __restrict__ W1,
    const float* __restrict__ W2, float* __restrict__ C1,
    float* __restrict__ C2, int K)
{
    __shared__ float sA [16][64];
    __shared__ float sW1[16][128];
    __shared__ float sW2[16][128];

    const int tid = threadIdx.x;
    const int tx = tid & 15, ty = tid >> 4;
    const int m0 = blockIdx.x * 64;
    const int r0 = ty * 4, c0 = tx * 8;

    unsigned long long acc1[4][4], acc2[4][4];
    #pragma unroll
    for (int i = 0; i < 4; i++)
        #pragma unroll
        for (int j = 0; j < 4; j++) { acc1[i][j] = 0ULL; acc2[i][j] = 0ULL; }

    for (int kt = 0; kt < K; kt += 16) {
        {   // A tile [64 x 16]
            int m = tid >> 2, kk = (tid & 3) * 4;
            float4 a = *(const float4*)&A[(size_t)(m0 + m) * K + kt + kk];
            if (RELU_A) {
                a.x = fmaxf(a.x, 0.f); a.y = fmaxf(a.y, 0.f);
                a.z = fmaxf(a.z, 0.f); a.w = fmaxf(a.w, 0.f);
            }
            sA[kk + 0][m] = a.x; sA[kk + 1][m] = a.y;
            sA[kk + 2][m] = a.z; sA[kk + 3][m] = a.w;
        }
        #pragma unroll
        for (int j = 0; j < 2; j++) {   // W tiles [16 x 128] each
            int idx4 = tid * 2 + j;     // 0..511
            int kk = idx4 >> 5, c4 = idx4 & 31;
            *(float4*)&sW1[kk][c4 * 4] = *(const float4*)&W1[(size_t)(kt + kk) * 128 + c4 * 4];
            *(float4*)&sW2[kk][c4 * 4] = *(const float4*)&W2[(size_t)(kt + kk) * 128 + c4 * 4];
        }
        __syncthreads();

        #pragma unroll
        for (int kk = 0; kk < 16; kk++) {
            float4 av = *(float4*)&sA[kk][r0];
            unsigned long long ap[4] = {bcast2(av.x), bcast2(av.y), bcast2(av.z), bcast2(av.w)};
            ulonglong2 w1a = *(ulonglong2*)&sW1[kk][c0];
            ulonglong2 w1b = *(ulonglong2*)&sW1[kk][c0 + 4];
            ulonglong2 w2a = *(ulonglong2*)&sW2[kk][c0];
            ulonglong2 w2b = *(ulonglong2*)&sW2[kk][c0 + 4];
            unsigned long long w1p[4] = {w1a.x, w1a.y, w1b.x, w1b.y};
            unsigned long long w2p[4] = {w2a.x, w2a.y, w2b.x, w2b.y};
            #pragma unroll
            for (int i = 0; i < 4; i++)
                #pragma unroll
                for (int j = 0; j < 4; j++) {
                    ffma2(acc1[i][j], ap[i], w1p[j]);
                    ffma2(acc2[i][j], ap[i], w2p[j]);
                }
        }
        __syncthreads();
    }

    #pragma unroll
    for (int i = 0; i < 4; i++) {
        size_t row = (size_t)(m0 + r0 + i) * 128 + c0;
        ulonglong2 s;
        s.x = acc1[i][0]; s.y = acc1[i][1]; *(ulonglong2*)&C1[row]     = s;
        s.x = acc1[i][2]; s.y = acc1[i][3]; *(ulonglong2*)&C1[row + 4] = s;
        s.x = acc2[i][0]; s.y = acc2[i][1]; *(ulonglong2*)&C2[row]     = s;
        s.x = acc2[i][2]; s.y = acc2[i][3]; *(ulonglong2*)&C2[row + 4] = s;
    }
}

// ---------------- edge scatter: pre[dst] += msg[src]  (red.v4) ----------------
// edge_index is [2, E] row-major; dst row at word offset E*stride.
__global__ void scatter_k(const int* __restrict__ eidx,
                          const float* __restrict__ msg, float* __restrict__ pre, int E)
{
    int idx = blockIdx.x * blockDim.x + threadIdx.x;
    int total = E * 32;
    if (idx >= total) return;
    int e = idx >> 5, c4 = idx & 31;
    int st = g_idx_stride;
    int s = eidx[(size_t)e * st];
    int d = eidx[(size_t)(e + E) * st];
    float4 m = ((const float4*)msg)[(size_t)s * 32 + c4];
    float* p = &pre[(size_t)d * 128 + c4 * 4];
    asm volatile("red.global.add.v4.f32 [%0], {%1, %2, %3, %4};"
                 :: "l"(p), "f"(m.x), "f"(m.y), "f"(m.z), "f"(m.w) : "memory");
}

// ---------------- pair build ----------------
__global__ void pair_build_k(const int* __restrict__ pu, const int* __restrict__ pv,
                             const float* __restrict__ iso,
                             const float* __restrict__ HA, const float* __restrict__ HB,
                             const float* __restrict__ MA, const float* __restrict__ MB,
                             const float* __restrict__ w1r, const float* __restrict__ w2r,
                             float* __restrict__ pre2, float* __restrict__ msg2)
{
    int idx = blockIdx.x * blockDim.x + threadIdx.x;
    const int total = PTOT * 32;
    if (idx >= total) return;
    int p = idx >> 5, c4 = idx & 31;
    int st = g_idx_stride;
    int u = pu[(size_t)p * st];
    int v = pv[(size_t)p * st];
    float is = iso[p];

    float4 a = ((const float4*)HA)[(size_t)u * 32 + c4];
    float4 b = ((const float4*)HB)[(size_t)v * 32 + c4];
    float4 w = ((const float4*)w1r)[c4];
    float4 o;
    o.x = a.x + b.x + is * w.x; o.y = a.y + b.y + is * w.y;
    o.z = a.z + b.z + is * w.z; o.w = a.w + b.w + is * w.w;
    ((float4*)pre2)[(size_t)p * 32 + c4] = o;

    float4 ma = ((const float4*)MA)[(size_t)u * 32 + c4];
    float4 mb = ((const float4*)MB)[(size_t)v * 32 + c4];
    float4 w2 = ((const float4*)w2r)[c4];
    float4 m;
    m.x = ma.x + mb.x + is * w2.x; m.y = ma.y + mb.y + is * w2.y;
    m.z = ma.z + mb.z + is * w2.z; m.w = ma.w + mb.w + is * w2.w;
    ((float4*)msg2)[(size_t)p * 32 + c4] = m;
}

// ---------------- graph embeddings (relu applied on load) ----------------
__global__ void zero_comb_k(float* __restrict__ comb)
{
    int i = blockIdx.x * blockDim.x + threadIdx.x;
    if (i < BGR * 2 * HID) comb[i] = 0.f;
}

__global__ void ge1_k(const float* __restrict__ pre, float* __restrict__ comb)
{
    int g = blockIdx.x, c = threadIdx.x;
    float s = 0.f;
    for (int i = 0; i < NPG; i++)
        s += fmaxf(pre[(size_t)(g * NPG + i) * HID + c], 0.f);
    comb[g * 256 + c] = s;
}

__global__ void ge2_k(const float* __restrict__ pre2, float* __restrict__ comb)
{
    int g = blockIdx.x, chunk = blockIdx.y, c = threadIdx.x;
    int rbeg = chunk * 252, rend = rbeg + 252;   // 2016 = 8 * 252
    float s = 0.f;
    for (int i = rbeg; i < rend; i++) {
        float v = pre2[(size_t)(g * PPG + i) * HID + c];
        s += fmaxf(v, 0.f);
    }
    atomicAdd(&comb[g * 256 + 128 + c], s);
}

// ---------------- final classifier ----------------
__global__ void final_k(const float* __restrict__ comb,
                        const float* __restrict__ W0, const float* __restrict__ b0,
                        const float* __restrict__ W1, const float* __restrict__ b1,
                        float* __restrict__ out)
{
    __shared__ float sc[256];
    __shared__ float shc[128];
    int g = blockIdx.x, tid = threadIdx.x;
    sc[tid] = comb[g * 256 + tid];
    sc[tid + 128] = comb[g * 256 + 128 + tid];
    __syncthreads();

    float acc = b0[tid];
    #pragma unroll 8
    for (int k = 0; k < 256; k++) acc += sc[k] * W0[(size_t)k * 128 + tid];
    shc[tid] = fmaxf(acc, 0.f);
    __syncthreads();

    if (tid < OUTD) {
        float o = b1[tid];
        #pragma unroll 8
        for (int k = 0; k < 128; k++) o += shc[k] * W1[(size_t)k * OUTD + tid];
        out[g * OUTD + tid] = o;
    }
}

// ---------------- launch ----------------
extern "C" void kernel_launch(void* const* d_in, const int* in_sizes, int n_in,
                              void* d_out, int out_size)
{
    const float* x      = (const float*)d_in[0];
    const float* W1_0   = (const float*)d_in[1];
    const float* W2_0   = (const float*)d_in[2];
    const float* W1_1   = (const float*)d_in[3];
    const float* W2_1   = (const float*)d_in[4];
    const float* W1_2   = (const float*)d_in[5];
    const float* W2_2   = (const float*)d_in[6];
    const float* kW10   = (const float*)d_in[7];   // [257,128]
    const float* kW20   = (const float*)d_in[8];   // [257,128]
    const float* kW11   = (const float*)d_in[9];   // [128,128]
    const float* kW21   = (const float*)d_in[10];  // [128,128]
    const float* cW0    = (const float*)d_in[11];  // [256,128]
    const float* cb0    = (const float*)d_in[12];
    const float* cW1    = (const float*)d_in[13];  // [128,10]
    const float* cb1    = (const float*)d_in[14];
    const float* iso    = (const float*)d_in[15];  // [129024]
    const int*   ei     = (const int*)d_in[16];    // [2,E1] words
    const int*   batch  = (const int*)d_in[17];
    const int*   pu     = (const int*)d_in[18];
    const int*   pv     = (const int*)d_in[19];
    const int*   te     = (const int*)d_in[20];    // [2,E2] words
    float*       out    = (float*)d_out;

    const int E1 = in_sizes[16] / 2;
    const int E2 = in_sizes[20] / 2;

    float *bufA, *bufB, *msgN, *HA, *HB, *MA, *MB, *pre2, *h2, *M2, *comb;
    cudaGetSymbolAddress((void**)&bufA, g_bufA);
    cudaGetSymbolAddress((void**)&bufB, g_bufB);
    cudaGetSymbolAddress((void**)&msgN, g_msgN);
    cudaGetSymbolAddress((void**)&HA,   g_HA);
    cudaGetSymbolAddress((void**)&HB,   g_HB);
    cudaGetSymbolAddress((void**)&MA,   g_MA);
    cudaGetSymbolAddress((void**)&MB,   g_MB);
    cudaGetSymbolAddress((void**)&pre2, g_pre2);
    cudaGetSymbolAddress((void**)&h2,   g_h2);
    cudaGetSymbolAddress((void**)&M2,   g_M2);
    cudaGetSymbolAddress((void**)&comb, g_comb);

    detect_stride_k<<<1, 32>>>(batch);

    const int sblocks = (E1 * 32 + 255) / 256;

    // node GNN, 3 layers (relu fused into next layer's A load)
    gemm2f2_k<0><<<NN / 64, 256>>>(x,    W1_0, W2_0, bufA, msgN, 64);
    scatter_k<<<sblocks, 256>>>(ei, msgN, bufA, E1);

    gemm2f2_k<1><<<NN / 64, 256>>>(bufA, W1_1, W2_1, bufB, msgN, 128);
    scatter_k<<<sblocks, 256>>>(ei, msgN, bufB, E1);

    gemm2f2_k<1><<<NN / 64, 256>>>(bufB, W1_2, W2_2, bufA, msgN, 128);
    scatter_k<<<sblocks, 256>>>(ei, msgN, bufA, E1);
    // final node pre-activation lives in bufA; h = relu(bufA) applied on loads

    // 2-set input layer, decomposed: two_x@W = (h@W[:128])[u] + (h@W[128:256])[v] + iso*W[256]
    gemm2f2_k<1><<<NN / 64, 256>>>(bufA, kW10, kW10 + 128 * 128, HA, HB, 128);
    gemm2f2_k<1><<<NN / 64, 256>>>(bufA, kW20, kW20 + 128 * 128, MA, MB, 128);

    pair_build_k<<<(PTOT * 32 + 255) / 256, 256>>>(
        pu, pv, iso, HA, HB, MA, MB,
        kW10 + 256 * 128, kW20 + 256 * 128, pre2, M2);

    const int s2blocks = (E2 * 32 + 255) / 256;
    scatter_k<<<s2blocks, 256>>>(te, M2, pre2, E2);

    // 2-set layer 1 (dominant GEMM pair); relu(pre2) fused into A load
    gemm2f2_k<1><<<PTOT / 64, 256>>>(pre2, kW11, kW21, h2, M2, 128);
    scatter_k<<<s2blocks, 256>>>(te, M2, h2, E2);

    // readout
    zero_comb_k<<<(BGR * 256 + 255) / 256, 256>>>(comb);
    ge1_k<<<BGR, 128>>>(bufA, comb);
    dim3 g2grid(BGR, 8);
    ge2_k<<<g2grid, 128>>>(h2, comb);
    final_k<<<BGR, 128>>>(comb, cW0, cb0, cW1, cb1, out);
}

// round 4
// speedup vs baseline: 1.6549x; 1.3448x over previous
#include <cuda_runtime.h>

// ---------------- problem constants ----------------
#define HID   128
#define BGR   64       // graphs
#define NPG   64       // nodes per graph
#define NN    4096     // total nodes (BGR*NPG)
#define PPG   2016     // pairs per graph
#define PTOT  129024   // total pairs (BGR*PPG)
#define OUTD  10

// ---------------- device scratch (no allocation allowed) ----------------
__device__ float g_bufA[NN * HID];
__device__ float g_bufB[NN * HID];
__device__ float g_msgN[NN * HID];
__device__ float g_HA  [NN * HID];
__device__ float g_HB  [NN * HID];
__device__ float g_MA  [NN * HID];
__device__ float g_MB  [NN * HID];
__device__ float g_pre2[(size_t)PTOT * HID];   // 66 MB
__device__ float g_h2  [(size_t)PTOT * HID];   // 66 MB
__device__ float g_M2  [(size_t)PTOT * HID];   // 66 MB
__device__ float g_comb[BGR * 2 * HID];
__device__ int   g_idx_stride;                 // 1 if indices int32, 2 if int64

// ---------------- index dtype detection ----------------
// batch = repeat(arange(64), 64). Viewed as int32 words:
//   int32 layout -> word[64] == 1 ; int64 layout -> word[64] == 0.
__global__ void detect_stride_k(const int* __restrict__ batch_words) {
    if (threadIdx.x == 0) g_idx_stride = (batch_words[64] == 1) ? 1 : 2;
}

// ---------------- packed f32x2 helpers ----------------
__device__ __forceinline__ void ffma2(unsigned long long& acc,
                                      unsigned long long a,
                                      unsigned long long b) {
    asm("fma.rn.f32x2 %0, %1, %2, %0;" : "+l"(acc) : "l"(a), "l"(b));
}
__device__ __forceinline__ unsigned long long bcast2(float x) {
    unsigned long long d;
    asm("mov.b64 %0, {%1, %1};" : "=l"(d) : "f"(x));
    return d;
}

// ============================================================
// BIG dual GEMM: C1 = A'@W1, C2 = A'@W2, tile 128x128, 512 thr
// thread tile: 8 rows x 4 cols per C. Register double-buffered.
// ============================================================
template <int RELU_A>
__global__ __launch_bounds__(512) void gemmbig_k(
    const float* __restrict__ A, const float* __restrict__ W1,
    const float* __restrict__ W2, float* __restrict__ C1,
    float* __restrict__ C2, int K)
{
    __shared__ float sA [16][128];
    __shared__ float sW1[16][128];
    __shared__ float sW2[16][128];

    const int tid = threadIdx.x;
    const int tx = tid & 31, ty = tid >> 5;
    const int m0 = blockIdx.x * 128;
    const int r0 = ty * 8, c0 = tx * 4;

    // global-load indices
    const int am = tid >> 2, ak = (tid & 3) * 4;   // A: row am, k-off ak
    const int wk = tid >> 5, wc = (tid & 31) * 4;  // W: k-row wk, col wc

    unsigned long long acc1[8][2], acc2[8][2];
    #pragma unroll
    for (int i = 0; i < 8; i++) {
        acc1[i][0] = 0ULL; acc1[i][1] = 0ULL;
        acc2[i][0] = 0ULL; acc2[i][1] = 0ULL;
    }

    // preload tile 0 into registers
    float4 ra  = *(const float4*)&A [(size_t)(m0 + am) * K + ak];
    float4 rw1 = *(const float4*)&W1[(size_t)wk * 128 + wc];
    float4 rw2 = *(const float4*)&W2[(size_t)wk * 128 + wc];

    for (int kt = 0; kt < K; kt += 16) {
        // commit current tile to smem
        float4 a = ra;
        if (RELU_A) {
            a.x = fmaxf(a.x, 0.f); a.y = fmaxf(a.y, 0.f);
            a.z = fmaxf(a.z, 0.f); a.w = fmaxf(a.w, 0.f);
        }
        sA[ak + 0][am] = a.x; sA[ak + 1][am] = a.y;
        sA[ak + 2][am] = a.z; sA[ak + 3][am] = a.w;
        *(float4*)&sW1[wk][wc] = rw1;
        *(float4*)&sW2[wk][wc] = rw2;
        __syncthreads();

        // prefetch next tile (in flight during compute)
        if (kt + 16 < K) {
            ra  = *(const float4*)&A [(size_t)(m0 + am) * K + kt + 16 + ak];
            rw1 = *(const float4*)&W1[(size_t)(kt + 16 + wk) * 128 + wc];
            rw2 = *(const float4*)&W2[(size_t)(kt + 16 + wk) * 128 + wc];
        }

        #pragma unroll
        for (int kk = 0; kk < 16; kk++) {
            float4 a0 = *(float4*)&sA[kk][r0];
            float4 a1 = *(float4*)&sA[kk][r0 + 4];
            unsigned long long ap[8] = {
                bcast2(a0.x), bcast2(a0.y), bcast2(a0.z), bcast2(a0.w),
                bcast2(a1.x), bcast2(a1.y), bcast2(a1.z), bcast2(a1.w)};
            ulonglong2 w1 = *(ulonglong2*)&sW1[kk][c0];
            ulonglong2 w2 = *(ulonglong2*)&sW2[kk][c0];
            #pragma unroll
            for (int i = 0; i < 8; i++) {
                ffma2(acc1[i][0], ap[i], w1.x);
                ffma2(acc1[i][1], ap[i], w1.y);
                ffma2(acc2[i][0], ap[i], w2.x);
                ffma2(acc2[i][1], ap[i], w2.y);
            }
        }
        __syncthreads();
    }

    #pragma unroll
    for (int i = 0; i < 8; i++) {
        size_t row = (size_t)(m0 + r0 + i) * 128 + c0;
        ulonglong2 s;
        s.x = acc1[i][0]; s.y = acc1[i][1]; *(ulonglong2*)&C1[row] = s;
        s.x = acc2[i][0]; s.y = acc2[i][1]; *(ulonglong2*)&C2[row] = s;
    }
}

// ============================================================
// SMALL dual GEMM: tile 32x128, 256 thr, thread tile 2x8 per C.
// Low regs -> multiple CTAs/SM; grid = M/32 covers the chip.
// ============================================================
template <int RELU_A>
__global__ __launch_bounds__(256) void gemmsmall_k(
    const float* __restrict__ A, const float* __restrict__ W1,
    const float* __restrict__ W2, float* __restrict__ C1,
    float* __restrict__ C2, int K)
{
    __shared__ float sA [16][32];
    __shared__ float sW1[16][128];
    __shared__ float sW2[16][128];

    const int tid = threadIdx.x;
    const int tx = tid & 15, ty = tid >> 4;
    const int m0 = blockIdx.x * 32;
    const int r0 = ty * 2, c0 = tx * 8;

    unsigned long long acc1[2][4], acc2[2][4];
    #pragma unroll
    for (int i = 0; i < 2; i++)
        #pragma unroll
        for (int j = 0; j < 4; j++) { acc1[i][j] = 0ULL; acc2[i][j] = 0ULL; }

    for (int kt = 0; kt < K; kt += 16) {
        if (tid < 128) {   // A tile [32 x 16] = 128 float4
            int m = tid >> 2, kk = (tid & 3) * 4;
            float4 a = *(const float4*)&A[(size_t)(m0 + m) * K + kt + kk];
            if (RELU_A) {
                a.x = fmaxf(a.x, 0.f); a.y = fmaxf(a.y, 0.f);
                a.z = fmaxf(a.z, 0.f); a.w = fmaxf(a.w, 0.f);
            }
            sA[kk + 0][m] = a.x; sA[kk + 1][m] = a.y;
            sA[kk + 2][m] = a.z; sA[kk + 3][m] = a.w;
        }
        #pragma unroll
        for (int j = 0; j < 2; j++) {   // W tiles [16 x 128]
            int idx4 = tid * 2 + j;     // 0..511
            int kk = idx4 >> 5, c4 = idx4 & 31;
            *(float4*)&sW1[kk][c4 * 4] = *(const float4*)&W1[(size_t)(kt + kk) * 128 + c4 * 4];
            *(float4*)&sW2[kk][c4 * 4] = *(const float4*)&W2[(size_t)(kt + kk) * 128 + c4 * 4];
        }
        __syncthreads();

        #pragma unroll
        for (int kk = 0; kk < 16; kk++) {
            unsigned long long ap0 = bcast2(sA[kk][r0]);
            unsigned long long ap1 = bcast2(sA[kk][r0 + 1]);
            ulonglong2 w1a = *(ulonglong2*)&sW1[kk][c0];
            ulonglong2 w1b = *(ulonglong2*)&sW1[kk][c0 + 4];
            ulonglong2 w2a = *(ulonglong2*)&sW2[kk][c0];
            ulonglong2 w2b = *(ulonglong2*)&sW2[kk][c0 + 4];
            ffma2(acc1[0][0], ap0, w1a.x); ffma2(acc1[0][1], ap0, w1a.y);
            ffma2(acc1[0][2], ap0, w1b.x); ffma2(acc1[0][3], ap0, w1b.y);
            ffma2(acc1[1][0], ap1, w1a.x); ffma2(acc1[1][1], ap1, w1a.y);
            ffma2(acc1[1][2], ap1, w1b.x); ffma2(acc1[1][3], ap1, w1b.y);
            ffma2(acc2[0][0], ap0, w2a.x); ffma2(acc2[0][1], ap0, w2a.y);
            ffma2(acc2[0][2], ap0, w2b.x); ffma2(acc2[0][3], ap0, w2b.y);
            ffma2(acc2[1][0], ap1, w2a.x); ffma2(acc2[1][1], ap1, w2a.y);
            ffma2(acc2[1][2], ap1, w2b.x); ffma2(acc2[1][3], ap1, w2b.y);
        }
        __syncthreads();
    }

    #pragma unroll
    for (int i = 0; i < 2; i++) {
        size_t row = (size_t)(m0 + r0 + i) * 128 + c0;
        ulonglong2 s;
        s.x = acc1[i][0]; s.y = acc1[i][1]; *(ulonglong2*)&C1[row]     = s;
        s.x = acc1[i][2]; s.y = acc1[i][3]; *(ulonglong2*)&C1[row + 4] = s;
        s.x = acc2[i][0]; s.y = acc2[i][1]; *(ulonglong2*)&C2[row]     = s;
        s.x = acc2[i][2]; s.y = acc2[i][3]; *(ulonglong2*)&C2[row + 4] = s;
    }
}

// ---------------- edge scatter: pre[dst] += msg[src]  (red.v4) ----------------
__global__ void scatter_k(const int* __restrict__ eidx,
                          const float* __restrict__ msg, float* __restrict__ pre, int E)
{
    int idx = blockIdx.x * blockDim.x + threadIdx.x;
    int total = E * 32;
    if (idx >= total) return;
    int e = idx >> 5, c4 = idx & 31;
    int st = g_idx_stride;
    int s = eidx[(size_t)e * st];
    int d = eidx[(size_t)(e + E) * st];
    float4 m = ((const float4*)msg)[(size_t)s * 32 + c4];
    float* p = &pre[(size_t)d * 128 + c4 * 4];
    asm volatile("red.global.add.v4.f32 [%0], {%1, %2, %3, %4};"
                 :: "l"(p), "f"(m.x), "f"(m.y), "f"(m.z), "f"(m.w) : "memory");
}

// ---------------- pair build ----------------
__global__ void pair_build_k(const int* __restrict__ pu, const int* __restrict__ pv,
                             const float* __restrict__ iso,
                             const float* __restrict__ HA, const float* __restrict__ HB,
                             const float* __restrict__ MA, const float* __restrict__ MB,
                             const float* __restrict__ w1r, const float* __restrict__ w2r,
                             float* __restrict__ pre2, float* __restrict__ msg2)
{
    int idx = blockIdx.x * blockDim.x + threadIdx.x;
    const int total = PTOT * 32;
    if (idx >= total) return;
    int p = idx >> 5, c4 = idx & 31;
    int st = g_idx_stride;
    int u = pu[(size_t)p * st];
    int v = pv[(size_t)p * st];
    float is = iso[p];

    float4 a = ((const float4*)HA)[(size_t)u * 32 + c4];
    float4 b = ((const float4*)HB)[(size_t)v * 32 + c4];
    float4 w = ((const float4*)w1r)[c4];
    float4 o;
    o.x = a.x + b.x + is * w.x; o.y = a.y + b.y + is * w.y;
    o.z = a.z + b.z + is * w.z; o.w = a.w + b.w + is * w.w;
    ((float4*)pre2)[(size_t)p * 32 + c4] = o;

    float4 ma = ((const float4*)MA)[(size_t)u * 32 + c4];
    float4 mb = ((const float4*)MB)[(size_t)v * 32 + c4];
    float4 w2 = ((const float4*)w2r)[c4];
    float4 m;
    m.x = ma.x + mb.x + is * w2.x; m.y = ma.y + mb.y + is * w2.y;
    m.z = ma.z + mb.z + is * w2.z; m.w = ma.w + mb.w + is * w2.w;
    ((float4*)msg2)[(size_t)p * 32 + c4] = m;
}

// ---------------- graph embeddings (relu applied on load) ----------------
__global__ void zero_comb_k(float* __restrict__ comb)
{
    int i = blockIdx.x * blockDim.x + threadIdx.x;
    if (i < BGR * 2 * HID) comb[i] = 0.f;
}

__global__ void ge1_k(const float* __restrict__ pre, float* __restrict__ comb)
{
    int g = blockIdx.x, c = threadIdx.x;
    float s = 0.f;
    for (int i = 0; i < NPG; i++)
        s += fmaxf(pre[(size_t)(g * NPG + i) * HID + c], 0.f);
    comb[g * 256 + c] = s;
}

__global__ void ge2_k(const float* __restrict__ pre2, float* __restrict__ comb)
{
    int g = blockIdx.x, chunk = blockIdx.y, c = threadIdx.x;
    int rbeg = chunk * 252, rend = rbeg + 252;   // 2016 = 8 * 252
    float s = 0.f;
    for (int i = rbeg; i < rend; i++) {
        float v = pre2[(size_t)(g * PPG + i) * HID + c];
        s += fmaxf(v, 0.f);
    }
    atomicAdd(&comb[g * 256 + 128 + c], s);
}

// ---------------- final classifier ----------------
__global__ void final_k(const float* __restrict__ comb,
                        const float* __restrict__ W0, const float* __restrict__ b0,
                        const float* __restrict__ W1, const float* __restrict__ b1,
                        float* __restrict__ out)
{
    __shared__ float sc[256];
    __shared__ float shc[128];
    int g = blockIdx.x, tid = threadIdx.x;
    sc[tid] = comb[g * 256 + tid];
    sc[tid + 128] = comb[g * 256 + 128 + tid];
    __syncthreads();

    float acc = b0[tid];
    #pragma unroll 8
    for (int k = 0; k < 256; k++) acc += sc[k] * W0[(size_t)k * 128 + tid];
    shc[tid] = fmaxf(acc, 0.f);
    __syncthreads();

    if (tid < OUTD) {
        float o = b1[tid];
        #pragma unroll 8
        for (int k = 0; k < 128; k++) o += shc[k] * W1[(size_t)k * OUTD + tid];
        out[g * OUTD + tid] = o;
    }
}

// ---------------- launch ----------------
extern "C" void kernel_launch(void* const* d_in, const int* in_sizes, int n_in,
                              void* d_out, int out_size)
{
    const float* x      = (const float*)d_in[0];
    const float* W1_0   = (const float*)d_in[1];
    const float* W2_0   = (const float*)d_in[2];
    const float* W1_1   = (const float*)d_in[3];
    const float* W2_1   = (const float*)d_in[4];
    const float* W1_2   = (const float*)d_in[5];
    const float* W2_2   = (const float*)d_in[6];
    const float* kW10   = (const float*)d_in[7];   // [257,128]
    const float* kW20   = (const float*)d_in[8];   // [257,128]
    const float* kW11   = (const float*)d_in[9];   // [128,128]
    const float* kW21   = (const float*)d_in[10];  // [128,128]
    const float* cW0    = (const float*)d_in[11];  // [256,128]
    const float* cb0    = (const float*)d_in[12];
    const float* cW1    = (const float*)d_in[13];  // [128,10]
    const float* cb1    = (const float*)d_in[14];
    const float* iso    = (const float*)d_in[15];  // [129024]
    const int*   ei     = (const int*)d_in[16];    // [2,E1] words
    const int*   batch  = (const int*)d_in[17];
    const int*   pu     = (const int*)d_in[18];
    const int*   pv     = (const int*)d_in[19];
    const int*   te     = (const int*)d_in[20];    // [2,E2] words
    float*       out    = (float*)d_out;

    const int E1 = in_sizes[16] / 2;
    const int E2 = in_sizes[20] / 2;

    float *bufA, *bufB, *msgN, *HA, *HB, *MA, *MB, *pre2, *h2, *M2, *comb;
    cudaGetSymbolAddress((void**)&bufA, g_bufA);
    cudaGetSymbolAddress((void**)&bufB, g_bufB);
    cudaGetSymbolAddress((void**)&msgN, g_msgN);
    cudaGetSymbolAddress((void**)&HA,   g_HA);
    cudaGetSymbolAddress((void**)&HB,   g_HB);
    cudaGetSymbolAddress((void**)&MA,   g_MA);
    cudaGetSymbolAddress((void**)&MB,   g_MB);
    cudaGetSymbolAddress((void**)&pre2, g_pre2);
    cudaGetSymbolAddress((void**)&h2,   g_h2);
    cudaGetSymbolAddress((void**)&M2,   g_M2);
    cudaGetSymbolAddress((void**)&comb, g_comb);

    detect_stride_k<<<1, 32>>>(batch);

    const int sblocks = (E1 * 32 + 255) / 256;

    // node GNN, 3 layers (relu fused into next layer's A load); grid = NN/32 = 128
    gemmsmall_k<0><<<NN / 32, 256>>>(x,    W1_0, W2_0, bufA, msgN, 64);
    scatter_k<<<sblocks, 256>>>(ei, msgN, bufA, E1);

    gemmsmall_k<1><<<NN / 32, 256>>>(bufA, W1_1, W2_1, bufB, msgN, 128);
    scatter_k<<<sblocks, 256>>>(ei, msgN, bufB, E1);

    gemmsmall_k<1><<<NN / 32, 256>>>(bufB, W1_2, W2_2, bufA, msgN, 128);
    scatter_k<<<sblocks, 256>>>(ei, msgN, bufA, E1);
    // node pre-activation in bufA; h = relu(bufA) applied on loads

    // 2-set input layer, decomposed
    gemmsmall_k<1><<<NN / 32, 256>>>(bufA, kW10, kW10 + 128 * 128, HA, HB, 128);
    gemmsmall_k<1><<<NN / 32, 256>>>(bufA, kW20, kW20 + 128 * 128, MA, MB, 128);

    pair_build_k<<<(PTOT * 32 + 255) / 256, 256>>>(
        pu, pv, iso, HA, HB, MA, MB,
        kW10 + 256 * 128, kW20 + 256 * 128, pre2, M2);

    const int s2blocks = (E2 * 32 + 255) / 256;
    scatter_k<<<s2blocks, 256>>>(te, M2, pre2, E2);

    // 2-set layer 1: the dominant GEMM pair; relu(pre2) fused into A load
    gemmbig_k<1><<<PTOT / 128, 512>>>(pre2, kW11, kW21, h2, M2, 128);
    scatter_k<<<s2blocks, 256>>>(te, M2, h2, E2);

    // readout
    zero_comb_k<<<(BGR * 256 + 255) / 256, 256>>>(comb);
    ge1_k<<<BGR, 128>>>(bufA, comb);
    dim3 g2grid(BGR, 8);
    ge2_k<<<g2grid, 128>>>(h2, comb);
    final_k<<<BGR, 128>>>(comb, cW0, cb0, cW1, cb1, out);
}

// round 5
// speedup vs baseline: 1.7017x; 1.0283x over previous
#include <cuda_runtime.h>

// ---------------- problem constants ----------------
#define HID   128
#define BGR   64       // graphs
#define NPG   64       // nodes per graph
#define NN    4096     // total nodes (BGR*NPG)
#define PPG   2016     // pairs per graph
#define PTOT  129024   // total pairs (BGR*PPG)
#define OUTD  10

// ---------------- device scratch (no allocation allowed) ----------------
__device__ float g_bufA[NN * HID];
__device__ float g_bufB[NN * HID];
__device__ float g_msgN[NN * HID];
__device__ float g_HA  [NN * HID];
__device__ float g_HB  [NN * HID];
__device__ float g_MA  [NN * HID];
__device__ float g_MB  [NN * HID];
__device__ float g_pre2[(size_t)PTOT * HID];   // 66 MB
__device__ float g_h2  [(size_t)PTOT * HID];   // 66 MB
__device__ float g_M2  [(size_t)PTOT * HID];   // 66 MB
__device__ float g_comb[BGR * 2 * HID];
__device__ int   g_idx_stride;                 // 1 if indices int32, 2 if int64

// ---------------- index dtype detection ----------------
__global__ void detect_stride_k(const int* __restrict__ batch_words) {
    if (threadIdx.x == 0) g_idx_stride = (batch_words[64] == 1) ? 1 : 2;
}

// ---------------- packed f32x2 helpers ----------------
__device__ __forceinline__ void ffma2(unsigned long long& acc,
                                      unsigned long long a,
                                      unsigned long long b) {
    asm("fma.rn.f32x2 %0, %1, %2, %0;" : "+l"(acc) : "l"(a), "l"(b));
}
__device__ __forceinline__ unsigned long long bcast2(float x) {
    unsigned long long d;
    asm("mov.b64 %0, {%1, %1};" : "=l"(d) : "f"(x));
    return d;
}

// ============================================================
// SMALL dual GEMM, whole-K resident: C1 = A'@W1, C2 = A'@W2
// tile 32 x 128, 256 threads, dynamic smem = K*128*8 + K*32*4 B
// One bulk load (high MLP), ONE sync, K iterations of pure FFMA2.
// ============================================================
template <int K, int RELU_A>
__global__ __launch_bounds__(256) void gemm_small_k(
    const float* __restrict__ A, const float* __restrict__ W1,
    const float* __restrict__ W2, float* __restrict__ C1,
    float* __restrict__ C2)
{
    extern __shared__ float smem[];
    float* sW1 = smem;               // [K][128]
    float* sW2 = smem + K * 128;     // [K][128]
    float* sA  = smem + 2 * K * 128; // [K][32] (k-major)

    const int tid = threadIdx.x;
    const int m0 = blockIdx.x * 32;

    // W tiles: linear coalesced float4
    #pragma unroll
    for (int i = 0; i < (K * 128 / 4) / 256; i++) {
        int idx = tid + i * 256;
        ((float4*)sW1)[idx] = ((const float4*)W1)[idx];
        ((float4*)sW2)[idx] = ((const float4*)W2)[idx];
    }
    // A tile, row-fast (conflict-free STS; L1 coalesces the 16B row reads)
    #pragma unroll
    for (int i = 0; i < (K * 32 / 4) / 256; i++) {
        int idx = tid + i * 256;
        int row = idx & 31, k4 = idx >> 5;
        float4 a = *(const float4*)&A[(size_t)(m0 + row) * K + k4 * 4];
        if (RELU_A) {
            a.x = fmaxf(a.x, 0.f); a.y = fmaxf(a.y, 0.f);
            a.z = fmaxf(a.z, 0.f); a.w = fmaxf(a.w, 0.f);
        }
        sA[(k4 * 4 + 0) * 32 + row] = a.x;
        sA[(k4 * 4 + 1) * 32 + row] = a.y;
        sA[(k4 * 4 + 2) * 32 + row] = a.z;
        sA[(k4 * 4 + 3) * 32 + row] = a.w;
    }
    __syncthreads();

    const int tx = tid & 15, ty = tid >> 4;
    const int r0 = ty * 2, c0 = tx * 8;

    unsigned long long acc1[2][4], acc2[2][4];
    #pragma unroll
    for (int i = 0; i < 2; i++)
        #pragma unroll
        for (int j = 0; j < 4; j++) { acc1[i][j] = 0ULL; acc2[i][j] = 0ULL; }

    #pragma unroll 16
    for (int kk = 0; kk < K; kk++) {
        unsigned long long a0 = bcast2(sA[kk * 32 + r0]);
        unsigned long long a1 = bcast2(sA[kk * 32 + r0 + 1]);
        ulonglong2 w1a = *(ulonglong2*)&sW1[kk * 128 + c0];
        ulonglong2 w1b = *(ulonglong2*)&sW1[kk * 128 + c0 + 4];
        ulonglong2 w2a = *(ulonglong2*)&sW2[kk * 128 + c0];
        ulonglong2 w2b = *(ulonglong2*)&sW2[kk * 128 + c0 + 4];
        ffma2(acc1[0][0], a0, w1a.x); ffma2(acc1[0][1], a0, w1a.y);
        ffma2(acc1[0][2], a0, w1b.x); ffma2(acc1[0][3], a0, w1b.y);
        ffma2(acc1[1][0], a1, w1a.x); ffma2(acc1[1][1], a1, w1a.y);
        ffma2(acc1[1][2], a1, w1b.x); ffma2(acc1[1][3], a1, w1b.y);
        ffma2(acc2[0][0], a0, w2a.x); ffma2(acc2[0][1], a0, w2a.y);
        ffma2(acc2[0][2], a0, w2b.x); ffma2(acc2[0][3], a0, w2b.y);
        ffma2(acc2[1][0], a1, w2a.x); ffma2(acc2[1][1], a1, w2a.y);
        ffma2(acc2[1][2], a1, w2b.x); ffma2(acc2[1][3], a1, w2b.y);
    }

    #pragma unroll
    for (int i = 0; i < 2; i++) {
        size_t row = (size_t)(m0 + r0 + i) * 128 + c0;
        ulonglong2 s;
        s.x = acc1[i][0]; s.y = acc1[i][1]; *(ulonglong2*)&C1[row]     = s;
        s.x = acc1[i][2]; s.y = acc1[i][3]; *(ulonglong2*)&C1[row + 4] = s;
        s.x = acc2[i][0]; s.y = acc2[i][1]; *(ulonglong2*)&C2[row]     = s;
        s.x = acc2[i][2]; s.y = acc2[i][3]; *(ulonglong2*)&C2[row + 4] = s;
    }
}

// ============================================================
// BIG dual GEMM, whole-K resident: tile 128 x 128, 512 threads
// dynamic smem = 192KB. thread tile 8x4 per C (fma-bound).
// ============================================================
template <int RELU_A>
__global__ __launch_bounds__(512) void gemm_big_k(
    const float* __restrict__ A, const float* __restrict__ W1,
    const float* __restrict__ W2, float* __restrict__ C1,
    float* __restrict__ C2)
{
    extern __shared__ float smem[];
    float* sW1 = smem;                 // [128][128]
    float* sW2 = smem + 128 * 128;     // [128][128]
    float* sA  = smem + 2 * 128 * 128; // [128][128] k-major

    const int tid = threadIdx.x;
    const int m0 = blockIdx.x * 128;

    #pragma unroll
    for (int i = 0; i < 8; i++) {      // 4096 f4 / 512 thr
        int idx = tid + i * 512;
        ((float4*)sW1)[idx] = ((const float4*)W1)[idx];
        ((float4*)sW2)[idx] = ((const float4*)W2)[idx];
    }
    #pragma unroll
    for (int i = 0; i < 8; i++) {
        int idx = tid + i * 512;
        int row = idx & 127, k4 = idx >> 7;
        float4 a = *(const float4*)&A[(size_t)(m0 + row) * 128 + k4 * 4];
        if (RELU_A) {
            a.x = fmaxf(a.x, 0.f); a.y = fmaxf(a.y, 0.f);
            a.z = fmaxf(a.z, 0.f); a.w = fmaxf(a.w, 0.f);
        }
        sA[(k4 * 4 + 0) * 128 + row] = a.x;
        sA[(k4 * 4 + 1) * 128 + row] = a.y;
        sA[(k4 * 4 + 2) * 128 + row] = a.z;
        sA[(k4 * 4 + 3) * 128 + row] = a.w;
    }
    __syncthreads();

    const int tx = tid & 31, ty = tid >> 5;
    const int r0 = ty * 8, c0 = tx * 4;

    unsigned long long acc1[8][2], acc2[8][2];
    #pragma unroll
    for (int i = 0; i < 8; i++) {
        acc1[i][0] = 0ULL; acc1[i][1] = 0ULL;
        acc2[i][0] = 0ULL; acc2[i][1] = 0ULL;
    }

    #pragma unroll 8
    for (int kk = 0; kk < 128; kk++) {
        float4 a0 = *(float4*)&sA[kk * 128 + r0];
        float4 a1 = *(float4*)&sA[kk * 128 + r0 + 4];
        unsigned long long ap[8] = {
            bcast2(a0.x), bcast2(a0.y), bcast2(a0.z), bcast2(a0.w),
            bcast2(a1.x), bcast2(a1.y), bcast2(a1.z), bcast2(a1.w)};
        ulonglong2 w1 = *(ulonglong2*)&sW1[kk * 128 + c0];
        ulonglong2 w2 = *(ulonglong2*)&sW2[kk * 128 + c0];
        #pragma unroll
        for (int i = 0; i < 8; i++) {
            ffma2(acc1[i][0], ap[i], w1.x);
            ffma2(acc1[i][1], ap[i], w1.y);
            ffma2(acc2[i][0], ap[i], w2.x);
            ffma2(acc2[i][1], ap[i], w2.y);
        }
    }

    #pragma unroll
    for (int i = 0; i < 8; i++) {
        size_t row = (size_t)(m0 + r0 + i) * 128 + c0;
        ulonglong2 s;
        s.x = acc1[i][0]; s.y = acc1[i][1]; *(ulonglong2*)&C1[row] = s;
        s.x = acc2[i][0]; s.y = acc2[i][1]; *(ulonglong2*)&C2[row] = s;
    }
}

// ---------------- edge scatter: pre[dst] += msg[src]  (red.v4) ----------------
__global__ void scatter_k(const int* __restrict__ eidx,
                          const float* __restrict__ msg, float* __restrict__ pre, int E)
{
    int idx = blockIdx.x * blockDim.x + threadIdx.x;
    int total = E * 32;
    if (idx >= total) return;
    int e = idx >> 5, c4 = idx & 31;
    int st = g_idx_stride;
    int s = eidx[(size_t)e * st];
    int d = eidx[(size_t)(e + E) * st];
    float4 m = ((const float4*)msg)[(size_t)s * 32 + c4];
    float* p = &pre[(size_t)d * 128 + c4 * 4];
    asm volatile("red.global.add.v4.f32 [%0], {%1, %2, %3, %4};"
                 :: "l"(p), "f"(m.x), "f"(m.y), "f"(m.z), "f"(m.w) : "memory");
}

// ---------------- pair build ----------------
__global__ void pair_build_k(const int* __restrict__ pu, const int* __restrict__ pv,
                             const float* __restrict__ iso,
                             const float* __restrict__ HA, const float* __restrict__ HB,
                             const float* __restrict__ MA, const float* __restrict__ MB,
                             const float* __restrict__ w1r, const float* __restrict__ w2r,
                             float* __restrict__ pre2, float* __restrict__ msg2)
{
    int idx = blockIdx.x * blockDim.x + threadIdx.x;
    const int total = PTOT * 32;
    if (idx >= total) return;
    int p = idx >> 5, c4 = idx & 31;
    int st = g_idx_stride;
    int u = pu[(size_t)p * st];
    int v = pv[(size_t)p * st];
    float is = iso[p];

    float4 a = ((const float4*)HA)[(size_t)u * 32 + c4];
    float4 b = ((const float4*)HB)[(size_t)v * 32 + c4];
    float4 w = ((const float4*)w1r)[c4];
    float4 o;
    o.x = a.x + b.x + is * w.x; o.y = a.y + b.y + is * w.y;
    o.z = a.z + b.z + is * w.z; o.w = a.w + b.w + is * w.w;
    ((float4*)pre2)[(size_t)p * 32 + c4] = o;

    float4 ma = ((const float4*)MA)[(size_t)u * 32 + c4];
    float4 mb = ((const float4*)MB)[(size_t)v * 32 + c4];
    float4 w2 = ((const float4*)w2r)[c4];
    float4 m;
    m.x = ma.x + mb.x + is * w2.x; m.y = ma.y + mb.y + is * w2.y;
    m.z = ma.z + mb.z + is * w2.z; m.w = ma.w + mb.w + is * w2.w;
    ((float4*)msg2)[(size_t)p * 32 + c4] = m;
}

// ---------------- graph embeddings (relu applied on load) ----------------
__global__ void zero_comb_k(float* __restrict__ comb)
{
    int i = blockIdx.x * blockDim.x + threadIdx.x;
    if (i < BGR * 2 * HID) comb[i] = 0.f;
}

__global__ void ge1_k(const float* __restrict__ pre, float* __restrict__ comb)
{
    int g = blockIdx.x, c = threadIdx.x;
    float s = 0.f;
    for (int i = 0; i < NPG; i++)
        s += fmaxf(pre[(size_t)(g * NPG + i) * HID + c], 0.f);
    comb[g * 256 + c] = s;
}

__global__ void ge2_k(const float* __restrict__ pre2, float* __restrict__ comb)
{
    int g = blockIdx.x, chunk = blockIdx.y, c = threadIdx.x;
    int rbeg = chunk * 252, rend = rbeg + 252;   // 2016 = 8 * 252
    float s = 0.f;
    for (int i = rbeg; i < rend; i++) {
        float v = pre2[(size_t)(g * PPG + i) * HID + c];
        s += fmaxf(v, 0.f);
    }
    atomicAdd(&comb[g * 256 + 128 + c], s);
}

// ---------------- final classifier ----------------
__global__ void final_k(const float* __restrict__ comb,
                        const float* __restrict__ W0, const float* __restrict__ b0,
                        const float* __restrict__ W1, const float* __restrict__ b1,
                        float* __restrict__ out)
{
    __shared__ float sc[256];
    __shared__ float shc[128];
    int g = blockIdx.x, tid = threadIdx.x;
    sc[tid] = comb[g * 256 + tid];
    sc[tid + 128] = comb[g * 256 + 128 + tid];
    __syncthreads();

    float acc = b0[tid];
    #pragma unroll 8
    for (int k = 0; k < 256; k++) acc += sc[k] * W0[(size_t)k * 128 + tid];
    shc[tid] = fmaxf(acc, 0.f);
    __syncthreads();

    if (tid < OUTD) {
        float o = b1[tid];
        #pragma unroll 8
        for (int k = 0; k < 128; k++) o += shc[k] * W1[(size_t)k * OUTD + tid];
        out[g * OUTD + tid] = o;
    }
}

// ---------------- launch ----------------
extern "C" void kernel_launch(void* const* d_in, const int* in_sizes, int n_in,
                              void* d_out, int out_size)
{
    const float* x      = (const float*)d_in[0];
    const float* W1_0   = (const float*)d_in[1];
    const float* W2_0   = (const float*)d_in[2];
    const float* W1_1   = (const float*)d_in[3];
    const float* W2_1   = (const float*)d_in[4];
    const float* W1_2   = (const float*)d_in[5];
    const float* W2_2   = (const float*)d_in[6];
    const float* kW10   = (const float*)d_in[7];   // [257,128]
    const float* kW20   = (const float*)d_in[8];   // [257,128]
    const float* kW11   = (const float*)d_in[9];   // [128,128]
    const float* kW21   = (const float*)d_in[10];  // [128,128]
    const float* cW0    = (const float*)d_in[11];  // [256,128]
    const float* cb0    = (const float*)d_in[12];
    const float* cW1    = (const float*)d_in[13];  // [128,10]
    const float* cb1    = (const float*)d_in[14];
    const float* iso    = (const float*)d_in[15];  // [129024]
    const int*   ei     = (const int*)d_in[16];    // [2,E1] words
    const int*   batch  = (const int*)d_in[17];
    const int*   pu     = (const int*)d_in[18];
    const int*   pv     = (const int*)d_in[19];
    const int*   te     = (const int*)d_in[20];    // [2,E2] words
    float*       out    = (float*)d_out;

    const int E1 = in_sizes[16] / 2;
    const int E2 = in_sizes[20] / 2;

    float *bufA, *bufB, *msgN, *HA, *HB, *MA, *MB, *pre2, *h2, *M2, *comb;
    cudaGetSymbolAddress((void**)&bufA, g_bufA);
    cudaGetSymbolAddress((void**)&bufB, g_bufB);
    cudaGetSymbolAddress((void**)&msgN, g_msgN);
    cudaGetSymbolAddress((void**)&HA,   g_HA);
    cudaGetSymbolAddress((void**)&HB,   g_HB);
    cudaGetSymbolAddress((void**)&MA,   g_MA);
    cudaGetSymbolAddress((void**)&MB,   g_MB);
    cudaGetSymbolAddress((void**)&pre2, g_pre2);
    cudaGetSymbolAddress((void**)&h2,   g_h2);
    cudaGetSymbolAddress((void**)&M2,   g_M2);
    cudaGetSymbolAddress((void**)&comb, g_comb);

    // dynamic smem opt-in (idempotent; set on every call)
    const int SM_S64  = 64 * 128 * 8 + 64 * 32 * 4;     // 73728
    const int SM_S128 = 128 * 128 * 8 + 128 * 32 * 4;   // 147456
    const int SM_BIG  = 3 * 128 * 128 * 4;              // 196608
    cudaFuncSetAttribute(gemm_small_k<64, 0>,  cudaFuncAttributeMaxDynamicSharedMemorySize, SM_S64);
    cudaFuncSetAttribute(gemm_small_k<128, 1>, cudaFuncAttributeMaxDynamicSharedMemorySize, SM_S128);
    cudaFuncSetAttribute(gemm_big_k<1>,        cudaFuncAttributeMaxDynamicSharedMemorySize, SM_BIG);

    detect_stride_k<<<1, 32>>>(batch);

    const int sblocks = (E1 * 32 + 255) / 256;

    // node GNN, 3 layers (relu fused into next layer's A load)
    gemm_small_k<64, 0><<<NN / 32, 256, SM_S64>>>(x,    W1_0, W2_0, bufA, msgN);
    scatter_k<<<sblocks, 256>>>(ei, msgN, bufA, E1);

    gemm_small_k<128, 1><<<NN / 32, 256, SM_S128>>>(bufA, W1_1, W2_1, bufB, msgN);
    scatter_k<<<sblocks, 256>>>(ei, msgN, bufB, E1);

    gemm_small_k<128, 1><<<NN / 32, 256, SM_S128>>>(bufB, W1_2, W2_2, bufA, msgN);
    scatter_k<<<sblocks, 256>>>(ei, msgN, bufA, E1);
    // node pre-activation in bufA; h = relu(bufA) applied on loads

    // 2-set input layer, decomposed
    gemm_small_k<128, 1><<<NN / 32, 256, SM_S128>>>(bufA, kW10, kW10 + 128 * 128, HA, HB);
    gemm_small_k<128, 1><<<NN / 32, 256, SM_S128>>>(bufA, kW20, kW20 + 128 * 128, MA, MB);

    pair_build_k<<<(PTOT * 32 + 255) / 256, 256>>>(
        pu, pv, iso, HA, HB, MA, MB,
        kW10 + 256 * 128, kW20 + 256 * 128, pre2, M2);

    const int s2blocks = (E2 * 32 + 255) / 256;
    scatter_k<<<s2blocks, 256>>>(te, M2, pre2, E2);

    // 2-set layer 1: dominant GEMM pair; relu(pre2) fused into A load
    gemm_big_k<1><<<PTOT / 128, 512, SM_BIG>>>(pre2, kW11, kW21, h2, M2);
    scatter_k<<<s2blocks, 256>>>(te, M2, h2, E2);

    // readout
    zero_comb_k<<<(BGR * 256 + 255) / 256, 256>>>(comb);
    ge1_k<<<BGR, 128>>>(bufA, comb);
    dim3 g2grid(BGR, 8);
    ge2_k<<<g2grid, 128>>>(h2, comb);
    final_k<<<BGR, 128>>>(comb, cW0, cb0, cW1, cb1, out);
}